// round 17
// baseline (speedup 1.0000x reference)
#include <cuda_runtime.h>

#define NB      2
#define NPTS    8192
#define NDIM    64
#define KSEL    16
#define NSPLIT  4
#define CPT     (NPTS / NSPLIT)   // 2048 candidates per split
#define CHUNK_M 32                // candidates per smem chunk

// Scratch (allocation-free rule: __device__ globals).
__device__ float g_sq[NB * NPTS];
__device__ float g_pd[NB * NPTS * NSPLIT * KSEL];   // partial top-16 dists
__device__ int   g_pi[NB * NPTS * NSPLIT * KSEL];   // partial top-16 indices

// lexicographic (distance, index) ascending — stable top_k tie order
__device__ __forceinline__ bool keyless(float d1, int i1, float d2, int i2) {
    return (d1 < d2) || (d1 == d2 && i1 < i2);
}

// Branch-free insert into register-resident sorted-16 list (verified rounds 8/16).
__device__ __forceinline__ void ins16(float (&ld)[KSEL], int (&li)[KSEL],
                                      float dv, int idx) {
    int rank = 0;
#pragma unroll
    for (int p = 0; p < KSEL; p++)
        rank += keyless(ld[p], li[p], dv, idx) ? 1 : 0;
#pragma unroll
    for (int p = KSEL - 1; p > 0; p--) {
        bool here  = (p == rank);
        bool shift = (p > rank);
        ld[p] = here ? dv  : (shift ? ld[p - 1] : ld[p]);
        li[p] = here ? idx : (shift ? li[p - 1] : li[p]);
    }
    if (rank == 0) { ld[0] = dv; li[0] = idx; }
}

// ---------------------------------------------------------------------------
// Kernel 1: ||x||^2 per point, sequential fma chain c=0..63 (matches the dot
// chains below, so self-distance cancels to exactly 0 in fp32).
// ---------------------------------------------------------------------------
__global__ void norms_kernel(const float* __restrict__ x) {
    int p = blockIdx.x * blockDim.x + threadIdx.x;
    if (p >= NB * NPTS) return;
    int b = p >> 13;
    int n = p & (NPTS - 1);
    const float* xb = x + b * (NDIM * NPTS);
    float acc = 0.0f;
#pragma unroll
    for (int c = 0; c < NDIM; c++) {
        float v = xb[c * NPTS + n];
        acc = fmaf(v, v, acc);
    }
    g_sq[p] = acc;
}

// ---------------------------------------------------------------------------
// Kernel 2: split brute-force KNN with SMEM candidate staging.
//   Round 16's loop (register query, register top-16, 4 accumulator chains)
//   but candidates come via uniform LDS.128 broadcast (dedup'd, 1 crossbar
//   slot) instead of uniform LDG.128 (charged 32x at L1 return: 512B per
//   16B useful — the occupancy-invariant ~0.87 instr/cyc/SM cap of rounds
//   8/16). Block = 128 thr = 4 warps, ALL on the same split: one coalesced
//   candidate stream per block, chunked 64c x 32m (8KB) into smem.
//   blockIdx: split = blk & 3, query-block = blk >> 2 (128 queries).
// ---------------------------------------------------------------------------
__global__ __launch_bounds__(128, 4) void knn_split(const float* __restrict__ x) {
    __shared__ __align__(16) float4 tile4[NDIM * (CHUNK_M / 4)];   // 8 KB

    const int tid   = threadIdx.x;
    const int lane  = tid & 31;
    const int wid   = tid >> 5;                 // 0..3
    const int split = blockIdx.x & (NSPLIT - 1);
    const int qb    = blockIdx.x >> 2;          // 0..127
    const int gq    = qb * 128 + wid * 32 + lane;
    const int b     = gq >> 13;
    const int n     = gq & (NPTS - 1);
    const float* xb  = x + b * (NDIM * NPTS);
    const float* sqb = g_sq + b * NPTS;
    const float4* xg4 = reinterpret_cast<const float4*>(xb);

    // Query vector in registers (coalesced loads across lanes).
    float q[NDIM];
#pragma unroll
    for (int c = 0; c < NDIM; c++)
        q[c] = xb[c * NPTS + n];
    const float sqn = sqb[n];

    float ld[KSEL];
    int   li[KSEL];
#pragma unroll
    for (int p = 0; p < KSEL; p++) {
        ld[p] = __int_as_float(0x7f800000);   // +inf
        li[p] = 0x7fffffff;
    }

    const int m0 = split * CPT;
    for (int mbase = m0; mbase < m0 + CPT; mbase += CHUNK_M) {
        __syncthreads();   // previous chunk fully consumed

        // Cooperative coalesced load: 64 rows x 32 floats = 512 float4.
#pragma unroll
        for (int it = 0; it < 4; it++) {
            int i  = tid + it * 128;
            int c  = i >> 3;            // row
            int m4 = i & 7;             // float4 within row
            tile4[c * (CHUNK_M / 4) + m4] = xg4[c * (NPTS / 4) + (mbase >> 2) + m4];
        }
        __syncthreads();

        // 8 groups of 4 candidates; candidate reads are warp-uniform LDS.128.
#pragma unroll
        for (int g = 0; g < CHUNK_M / 4; g++) {
            float d0 = 0.f, d1 = 0.f, d2 = 0.f, d3 = 0.f;
#pragma unroll
            for (int c = 0; c < NDIM; c++) {
                float4 v = tile4[c * (CHUNK_M / 4) + g];   // broadcast
                d0 = fmaf(q[c], v.x, d0);
                d1 = fmaf(q[c], v.y, d1);
                d2 = fmaf(q[c], v.z, d2);
                d3 = fmaf(q[c], v.w, d3);
            }
            int m = mbase + 4 * g;
            float4 sm = *reinterpret_cast<const float4*>(sqb + m);  // uniform
            d0 = (sqn + (-2.0f * d0)) + sm.x;
            d1 = (sqn + (-2.0f * d1)) + sm.y;
            d2 = (sqn + (-2.0f * d2)) + sm.z;
            d3 = (sqn + (-2.0f * d3)) + sm.w;

            // Sequential m order -> stable lexicographic selection.
            if (d0 < ld[KSEL-1] || (d0 == ld[KSEL-1] && (m+0) < li[KSEL-1])) ins16(ld, li, d0, m+0);
            if (d1 < ld[KSEL-1] || (d1 == ld[KSEL-1] && (m+1) < li[KSEL-1])) ins16(ld, li, d1, m+1);
            if (d2 < ld[KSEL-1] || (d2 == ld[KSEL-1] && (m+2) < li[KSEL-1])) ins16(ld, li, d2, m+2);
            if (d3 < ld[KSEL-1] || (d3 == ld[KSEL-1] && (m+3) < li[KSEL-1])) ins16(ld, li, d3, m+3);
        }
    }

    // Write this split's sorted partial list.
    const int base = (gq * NSPLIT + split) * KSEL;
#pragma unroll
    for (int e = 0; e < KSEL; e++) {
        g_pd[base + e] = ld[e];
        g_pi[base + e] = li[e];
    }
}

// ---------------------------------------------------------------------------
// Kernel 3: exact 4-way merge of sorted partial lists + output.
// ---------------------------------------------------------------------------
__global__ void merge_kernel(float* __restrict__ out) {
    int gq = blockIdx.x * blockDim.x + threadIdx.x;
    if (gq >= NB * NPTS) return;
    int n = gq & (NPTS - 1);

    int head[NSPLIT];
    int lbase[NSPLIT];
#pragma unroll
    for (int s = 0; s < NSPLIT; s++) {
        head[s]  = 0;
        lbase[s] = (gq * NSPLIT + s) * KSEL;
    }

    int out0 = gq * KSEL;                       // plane 0: nn_idx
    int out1 = NB * NPTS * KSEL + out0;         // plane 1: center_idx
#pragma unroll
    for (int k = 0; k < KSEL; k++) {
        float bd = __int_as_float(0x7f800000);
        int   bi = 0x7fffffff;
        int   bs = 0;
        bool  first = true;
#pragma unroll
        for (int s = 0; s < NSPLIT; s++) {
            if (head[s] < KSEL) {
                float d = g_pd[lbase[s] + head[s]];
                int   i = g_pi[lbase[s] + head[s]];
                if (first || keyless(d, i, bd, bi)) { bd = d; bi = i; bs = s; first = false; }
            }
        }
        head[bs]++;
        out[out0 + k] = (float)bi;
        out[out1 + k] = (float)n;
    }
}

// ---------------------------------------------------------------------------
extern "C" void kernel_launch(void* const* d_in, const int* in_sizes, int n_in,
                              void* d_out, int out_size) {
    const float* x = (const float*)d_in[0];
    float* out = (float*)d_out;
    norms_kernel<<<(NB * NPTS + 255) / 256, 256>>>(x);
    knn_split<<<(NB * NPTS / 128) * NSPLIT, 128>>>(x);
    merge_kernel<<<(NB * NPTS + 127) / 128, 128>>>(out);
}